// round 2
// baseline (speedup 1.0000x reference)
#include <cuda_runtime.h>
#include <cuda_bf16.h>

typedef unsigned long long ull;

// Problem shapes (fixed)
#define BN 16
#define FN 4096
#define MN 512
#define DN 256
#define VEN 64
#define HN 512
#define OUTN 8
#define VN 50
#define INW (VEN + DN)   // 320
#define NSEG (BN * MN)   // 8192

#define NPB 512          // proj main blocks (4096 warps x 16 frames = 65536 frames)
#define FRPW 16          // frames per warp (contiguous)

// ---------------------------------------------------------------------------
// Device scratch (allocation-free)
// ---------------------------------------------------------------------------
__device__ __align__(16) ull   g_Wf[128 * OUTN];       // feature weights, f32x2 pairs:
                                                       // g_Wf[jp*8+k] = (Wc[64+2jp][k], Wc[64+2jp+1][k])
__device__ __align__(16) float g_WcEmb[VEN * OUTN];    // emb rows of Wc: [j][k]
__device__ __align__(16) float g_pe[VN * OUTN];        // per-vowel emb projection
__device__ __align__(16) float g_bc[OUTN];             // combined bias
__device__ __align__(16) float g_sum[NSEG * OUTN];     // segment sums of projected frames
__device__ __align__(16) float g_cnt[NSEG];            // segment counts

// ---------------------------------------------------------------------------
// f32x2 packed FMA (Blackwell)
// ---------------------------------------------------------------------------
__device__ __forceinline__ ull fma2(ull a, ull b, ull c) {
    ull d;
    asm("fma.rn.f32x2 %0, %1, %2, %3;" : "=l"(d) : "l"(a), "l"(b), "l"(c));
    return d;
}

// ---------------------------------------------------------------------------
// Kernel A: fold Wc = W_mora @ W_post (into packed layouts), bc, zero accum.
// Thread-per-(i,k): 2560 fold threads + 8 bias threads; rest zero g_sum/g_cnt.
// ---------------------------------------------------------------------------
__global__ __launch_bounds__(256) void fold_kernel(
    const float* __restrict__ W_mora,   // [320, 512]
    const float* __restrict__ b_mora,   // [512]
    const float* __restrict__ W_post,   // [512, 8]
    const float* __restrict__ b_post)   // [8]
{
    __shared__ float sWp[HN * OUTN];    // 16 KB
    const int tid = threadIdx.x;
    const int gt = blockIdx.x * 256 + tid;
    const int nthr = gridDim.x * 256;

    // zero accumulators (grid-stride, all blocks)
    for (int i = gt; i < NSEG * OUTN; i += nthr) g_sum[i] = 0.0f;
    for (int i = gt; i < NSEG; i += nthr) g_cnt[i] = 0.0f;

    if (blockIdx.x < 11) {
        // stage W_post in smem
        for (int i = tid; i < HN * OUTN / 4; i += 256)
            ((float4*)sWp)[i] = ((const float4*)W_post)[i];
        __syncthreads();

        if (gt < INW * OUTN) {
            const int i = gt >> 3, k = gt & 7;
            const float* wr = W_mora + i * HN;
            float s = 0.0f;
#pragma unroll 8
            for (int h = 0; h < HN; h++) s += wr[h] * sWp[h * OUTN + k];
            if (i < VEN) {
                g_WcEmb[i * OUTN + k] = s;
            } else {
                const int j = i - VEN;
                ((float*)g_Wf)[((j >> 1) * OUTN + k) * 2 + (j & 1)] = s;
            }
        } else if (gt < INW * OUTN + OUTN) {
            const int k = gt - INW * OUTN;
            float s = b_post[k];
            for (int h = 0; h < HN; h++) s += b_mora[h] * sWp[h * OUTN + k];
            g_bc[k] = s;
        }
    }
}

// ---------------------------------------------------------------------------
// Transposed warp reduction: input v[0..7] per lane (k-indexed partials),
// output: every lane returns full warp-sum for k = lane & 7. 9 shuffles.
// ---------------------------------------------------------------------------
__device__ __forceinline__ float warp_reduce_k(const float v[8], int lane) {
    const unsigned FULL = 0xFFFFFFFFu;
    float nv[4];
    const int b0 = lane & 1;
#pragma unroll
    for (int i = 0; i < 4; i++) {
        float keep = b0 ? v[2 * i + 1] : v[2 * i];
        float send = b0 ? v[2 * i]     : v[2 * i + 1];
        nv[i] = keep + __shfl_xor_sync(FULL, send, 1);
    }
    const int b1 = (lane >> 1) & 1;
    float mv[2];
#pragma unroll
    for (int i = 0; i < 2; i++) {
        float keep = b1 ? nv[2 * i + 1] : nv[2 * i];
        float send = b1 ? nv[2 * i]     : nv[2 * i + 1];
        mv[i] = keep + __shfl_xor_sync(FULL, send, 2);
    }
    const int b2 = (lane >> 2) & 1;
    float keep = b2 ? mv[1] : mv[0];
    float send = b2 ? mv[0] : mv[1];
    float s = keep + __shfl_xor_sync(FULL, send, 4);
    s += __shfl_xor_sync(FULL, s, 8);
    s += __shfl_xor_sync(FULL, s, 16);
    return s;   // k = lane & 7
}

__device__ __forceinline__ void flush_seg(const ull racc[8], float fcnt,
                                          int seg, int lane) {
    float v[8];
#pragma unroll
    for (int k = 0; k < 8; k++) {
        float lo = __int_as_float((int)(racc[k] & 0xFFFFFFFFull));
        float hi = __int_as_float((int)(racc[k] >> 32));
        v[k] = lo + hi;
    }
    float s = warp_reduce_k(v, lane);
    if (lane < 8) atomicAdd(g_sum + seg * OUTN + lane, s);
    else if (lane == 8) atomicAdd(g_cnt + seg, fcnt);
}

// ---------------------------------------------------------------------------
// Kernel B: project frames to 8 dims (f32x2 FMA), run-length segment batching,
// scatter via atomics. Extra blocks compute per-vowel embedding projection.
// ---------------------------------------------------------------------------
__global__ __launch_bounds__(256) void proj_kernel(
    const float* __restrict__ features,   // [B, F, D]
    const int* __restrict__ mora_index,   // [B, F]
    const float* __restrict__ emb_table)  // [V, VE]
{
    if (blockIdx.x >= NPB) {
        // per-vowel embedding projection: pe[v][k] = emb[v] . WcEmb[:,k]
        const int gt = (blockIdx.x - NPB) * 256 + threadIdx.x;
        if (gt < VN * OUTN) {
            const int v = gt >> 3, k = gt & 7;
            const float* e = emb_table + v * VEN;
            float s = 0.0f;
#pragma unroll 8
            for (int j = 0; j < VEN; j++) s += e[j] * g_WcEmb[j * OUTN + k];
            g_pe[gt] = s;
        }
        return;
    }

    const int lane = threadIdx.x & 31;
    const int warp = (blockIdx.x * 256 + threadIdx.x) >> 5;   // 0..4095

    // preload this lane's weight slice: rows jp in {2l, 2l+1, 64+2l, 64+2l+1}
    ull w[4][8];
    {
        const int jps0 = 2 * lane, jps2 = 64 + 2 * lane;
        const ulonglong2* Wf2 = (const ulonglong2*)g_Wf;
#pragma unroll
        for (int r = 0; r < 4; r++) {
            const int jp = (r < 2) ? (jps0 + r) : (jps2 + r - 2);
            const ulonglong2* row = Wf2 + jp * 4;   // 8 f32x2 = 4x 16B
#pragma unroll
            for (int q = 0; q < 4; q++) {
                ulonglong2 t = row[q];
                w[r][2 * q] = t.x; w[r][2 * q + 1] = t.y;
            }
        }
    }

    const int base = warp * FRPW;      // 16 contiguous frames; never crosses b
    const int b = base >> 12;          // / FN

    ull racc[8];
#pragma unroll
    for (int k = 0; k < 8; k++) racc[k] = 0ull;
    float fcnt = 0.0f;
    int curm = mora_index[base];

    for (int it = 0; it < FRPW; it++) {
        const int g = base + it;
        const int m = mora_index[g];
        if (m != curm) {                       // warp-uniform
            flush_seg(racc, fcnt, (b << 9) + curm, lane);
#pragma unroll
            for (int k = 0; k < 8; k++) racc[k] = 0ull;
            fcnt = 0.0f;
            curm = m;
        }
        const ulonglong2* fr = (const ulonglong2*)(features + (size_t)g * DN);
        ulonglong2 xa = fr[lane];        // dims 4l..4l+3
        ulonglong2 xb = fr[32 + lane];   // dims 128+4l..128+4l+3
#pragma unroll
        for (int k = 0; k < 8; k++) {
            racc[k] = fma2(xa.x, w[0][k],
                      fma2(xa.y, w[1][k],
                      fma2(xb.x, w[2][k],
                      fma2(xb.y, w[3][k], racc[k]))));
        }
        fcnt += 1.0f;
    }
    flush_seg(racc, fcnt, (b << 9) + curm, lane);
}

// ---------------------------------------------------------------------------
// Kernel C: finalize: out[b,m,k] = bc[k] + pe[vowel][k] + (cnt>0 ? sum/cnt : 0)
// ---------------------------------------------------------------------------
__global__ __launch_bounds__(256) void final_kernel(
    const int* __restrict__ vowels,       // [B, M]
    float* __restrict__ out)              // [B, M, 8]
{
    const int t = blockIdx.x * blockDim.x + threadIdx.x;
    if (t >= NSEG * OUTN) return;
    const int k = t & 7;
    const int row = t >> 3;

    const int v = vowels[row];
    float s = g_bc[k] + g_pe[v * OUTN + k];
    const float cnt = g_cnt[row];
    if (cnt > 0.0f) s += g_sum[t] / cnt;
    out[t] = s;
}

// ---------------------------------------------------------------------------
// launch
// ---------------------------------------------------------------------------
extern "C" void kernel_launch(void* const* d_in, const int* in_sizes, int n_in,
                              void* d_out, int out_size)
{
    const int*   vowels     = (const int*)d_in[0];
    const float* features   = (const float*)d_in[1];
    const int*   mora_index = (const int*)d_in[2];
    const float* emb_table  = (const float*)d_in[3];
    const float* W_mora     = (const float*)d_in[4];
    const float* b_mora     = (const float*)d_in[5];
    // d_in[6] = W_frame, d_in[7] = b_frame: dead branch, unused
    const float* W_post     = (const float*)d_in[8];
    const float* b_post     = (const float*)d_in[9];
    float* out = (float*)d_out;

    fold_kernel<<<80, 256>>>(W_mora, b_mora, W_post, b_post);
    proj_kernel<<<NPB + 2, 256>>>(features, mora_index, emb_table);
    final_kernel<<<(NSEG * OUTN + 255) / 256, 256>>>(vowels, out);
}

// round 3
// speedup vs baseline: 1.4032x; 1.4032x over previous
#include <cuda_runtime.h>
#include <cuda_bf16.h>

typedef unsigned long long ull;

// Problem shapes (fixed)
#define BN 16
#define FN 4096
#define MN 512
#define DN 256
#define VEN 64
#define HN 512
#define OUTN 8
#define VN 50
#define INW (VEN + DN)   // 320
#define NSEG (BN * MN)   // 8192

#define NPB 512          // proj main blocks (4096 warps x 16 frames = 65536 frames)
#define FRPW 16          // frames per warp (contiguous)

// ---------------------------------------------------------------------------
// Device scratch (allocation-free)
// ---------------------------------------------------------------------------
__device__ __align__(16) ull   g_Wf[128 * OUTN];       // feature weights, f32x2 pairs:
                                                       // g_Wf[jp*8+k] = (Wc[64+2jp][k], Wc[64+2jp+1][k])
__device__ __align__(16) float g_WcEmb[VEN * OUTN];    // emb rows of Wc: [j][k]
__device__ __align__(16) float g_pe[VN * OUTN];        // per-vowel emb projection
__device__ __align__(16) float g_bc[OUTN];             // combined bias
__device__ __align__(16) float g_sum[NSEG * OUTN];     // segment sums of projected frames
__device__ __align__(16) float g_cnt[NSEG];            // segment counts

// ---------------------------------------------------------------------------
// f32x2 packed FMA (Blackwell)
// ---------------------------------------------------------------------------
__device__ __forceinline__ ull fma2(ull a, ull b, ull c) {
    ull d;
    asm("fma.rn.f32x2 %0, %1, %2, %3;" : "=l"(d) : "l"(a), "l"(b), "l"(c));
    return d;
}

// ---------------------------------------------------------------------------
// Kernel A: fold Wc = W_mora @ W_post, bc; zero accumulators.
// One block per row i (blocks 0..319); block 320 does the bias.
// Per block: stage wr + W_post in smem (coalesced), split H across 256 threads
// (thread t: k = t&7, 16-element h-chunk = t>>3), 32-way smem reduce.
// ---------------------------------------------------------------------------
__global__ __launch_bounds__(256) void fold_kernel(
    const float* __restrict__ W_mora,   // [320, 512]
    const float* __restrict__ b_mora,   // [512]
    const float* __restrict__ W_post,   // [512, 8]
    const float* __restrict__ b_post)   // [8]
{
    __shared__ float swr[HN];           // 2 KB
    __shared__ float sWp[HN * OUTN];    // 16 KB
    __shared__ float sPart[32][9];      // padded

    const int tid = threadIdx.x;
    const int gt = blockIdx.x * 256 + tid;
    const int nthr = gridDim.x * 256;

    // zero accumulators (grid-stride, all blocks; ~1 iter/thread)
    for (int i = gt; i < NSEG * OUTN; i += nthr) g_sum[i] = 0.0f;
    for (int i = gt; i < NSEG; i += nthr) g_cnt[i] = 0.0f;

    const int k = tid & 7;
    const int c = tid >> 3;     // 0..31

    if (blockIdx.x < INW) {
        const int i = blockIdx.x;
        // coalesced staging: wr (128 float4) + W_post (1024 float4)
        if (tid < 128)
            ((float4*)swr)[tid] = ((const float4*)(W_mora + i * HN))[tid];
        for (int j = tid; j < HN * OUTN / 4; j += 256)
            ((float4*)sWp)[j] = ((const float4*)W_post)[j];
        __syncthreads();

        float s = 0.0f;
#pragma unroll
        for (int j = 0; j < 16; j++) {
            const int h = c * 16 + j;
            s += swr[h] * sWp[h * OUTN + k];
        }
        sPart[c][k] = s;
        __syncthreads();

        if (tid < OUTN) {
            float t = 0.0f;
#pragma unroll
            for (int c2 = 0; c2 < 32; c2++) t += sPart[c2][tid];
            if (i < VEN) {
                g_WcEmb[i * OUTN + tid] = t;
            } else {
                const int j = i - VEN;
                ((float*)g_Wf)[((j >> 1) * OUTN + tid) * 2 + (j & 1)] = t;
            }
        }
    } else if (blockIdx.x == INW) {
        // bias: bc[k] = b_post[k] + sum_h b_mora[h]*W_post[h][k]
        if (tid < 128)
            ((float4*)swr)[tid] = ((const float4*)b_mora)[tid];
        for (int j = tid; j < HN * OUTN / 4; j += 256)
            ((float4*)sWp)[j] = ((const float4*)W_post)[j];
        __syncthreads();

        float s = 0.0f;
#pragma unroll
        for (int j = 0; j < 16; j++) {
            const int h = c * 16 + j;
            s += swr[h] * sWp[h * OUTN + k];
        }
        sPart[c][k] = s;
        __syncthreads();

        if (tid < OUTN) {
            float t = b_post[tid];
#pragma unroll
            for (int c2 = 0; c2 < 32; c2++) t += sPart[c2][tid];
            g_bc[tid] = t;
        }
    }
}

// ---------------------------------------------------------------------------
// Transposed warp reduction: input v[0..7] per lane (k-indexed partials),
// output: every lane returns full warp-sum for k = lane & 7. 9 shuffles.
// ---------------------------------------------------------------------------
__device__ __forceinline__ float warp_reduce_k(const float v[8], int lane) {
    const unsigned FULL = 0xFFFFFFFFu;
    float nv[4];
    const int b0 = lane & 1;
#pragma unroll
    for (int i = 0; i < 4; i++) {
        float keep = b0 ? v[2 * i + 1] : v[2 * i];
        float send = b0 ? v[2 * i]     : v[2 * i + 1];
        nv[i] = keep + __shfl_xor_sync(FULL, send, 1);
    }
    const int b1 = (lane >> 1) & 1;
    float mv[2];
#pragma unroll
    for (int i = 0; i < 2; i++) {
        float keep = b1 ? nv[2 * i + 1] : nv[2 * i];
        float send = b1 ? nv[2 * i]     : nv[2 * i + 1];
        mv[i] = keep + __shfl_xor_sync(FULL, send, 2);
    }
    const int b2 = (lane >> 2) & 1;
    float keep = b2 ? mv[1] : mv[0];
    float send = b2 ? mv[0] : mv[1];
    float s = keep + __shfl_xor_sync(FULL, send, 4);
    s += __shfl_xor_sync(FULL, s, 8);
    s += __shfl_xor_sync(FULL, s, 16);
    return s;   // k = lane & 7
}

__device__ __forceinline__ void flush_seg(const ull racc[8], float fcnt,
                                          int seg, int lane) {
    float v[8];
#pragma unroll
    for (int k = 0; k < 8; k++) {
        float lo = __int_as_float((int)(racc[k] & 0xFFFFFFFFull));
        float hi = __int_as_float((int)(racc[k] >> 32));
        v[k] = lo + hi;
    }
    float s = warp_reduce_k(v, lane);
    if (lane < 8) atomicAdd(g_sum + seg * OUTN + lane, s);
    else if (lane == 8) atomicAdd(g_cnt + seg, fcnt);
}

// ---------------------------------------------------------------------------
// Kernel B: project frames to 8 dims (f32x2 FMA), run-length segment batching,
// scatter via atomics. Extra blocks compute per-vowel embedding projection.
// ---------------------------------------------------------------------------
__global__ __launch_bounds__(256) void proj_kernel(
    const float* __restrict__ features,   // [B, F, D]
    const int* __restrict__ mora_index,   // [B, F]
    const float* __restrict__ emb_table)  // [V, VE]
{
    if (blockIdx.x >= NPB) {
        // per-vowel embedding projection: pe[v][k] = emb[v] . WcEmb[:,k]
        const int gt = (blockIdx.x - NPB) * 256 + threadIdx.x;
        if (gt < VN * OUTN) {
            const int v = gt >> 3, k = gt & 7;
            const float* e = emb_table + v * VEN;
            float s = 0.0f;
#pragma unroll 8
            for (int j = 0; j < VEN; j++) s += e[j] * g_WcEmb[j * OUTN + k];
            g_pe[gt] = s;
        }
        return;
    }

    const int lane = threadIdx.x & 31;
    const int warp = (blockIdx.x * 256 + threadIdx.x) >> 5;   // 0..4095

    // preload this lane's weight slice: rows jp in {2l, 2l+1, 64+2l, 64+2l+1}
    ull w[4][8];
    {
        const int jps0 = 2 * lane, jps2 = 64 + 2 * lane;
        const ulonglong2* Wf2 = (const ulonglong2*)g_Wf;
#pragma unroll
        for (int r = 0; r < 4; r++) {
            const int jp = (r < 2) ? (jps0 + r) : (jps2 + r - 2);
            const ulonglong2* row = Wf2 + jp * 4;   // 8 f32x2 = 4x 16B
#pragma unroll
            for (int q = 0; q < 4; q++) {
                ulonglong2 t = row[q];
                w[r][2 * q] = t.x; w[r][2 * q + 1] = t.y;
            }
        }
    }

    const int base = warp * FRPW;      // 16 contiguous frames; never crosses b
    const int b = base >> 12;          // / FN

    ull racc[8];
#pragma unroll
    for (int k = 0; k < 8; k++) racc[k] = 0ull;
    float fcnt = 0.0f;
    int curm = mora_index[base];

    for (int it = 0; it < FRPW; it++) {
        const int g = base + it;
        const int m = mora_index[g];
        if (m != curm) {                       // warp-uniform
            flush_seg(racc, fcnt, (b << 9) + curm, lane);
#pragma unroll
            for (int k = 0; k < 8; k++) racc[k] = 0ull;
            fcnt = 0.0f;
            curm = m;
        }
        const ulonglong2* fr = (const ulonglong2*)(features + (size_t)g * DN);
        ulonglong2 xa = fr[lane];        // dims 4l..4l+3
        ulonglong2 xb = fr[32 + lane];   // dims 128+4l..128+4l+3
#pragma unroll
        for (int k = 0; k < 8; k++) {
            racc[k] = fma2(xa.x, w[0][k],
                      fma2(xa.y, w[1][k],
                      fma2(xb.x, w[2][k],
                      fma2(xb.y, w[3][k], racc[k]))));
        }
        fcnt += 1.0f;
    }
    flush_seg(racc, fcnt, (b << 9) + curm, lane);
}

// ---------------------------------------------------------------------------
// Kernel C: finalize: out[b,m,k] = bc[k] + pe[vowel][k] + (cnt>0 ? sum/cnt : 0)
// ---------------------------------------------------------------------------
__global__ __launch_bounds__(256) void final_kernel(
    const int* __restrict__ vowels,       // [B, M]
    float* __restrict__ out)              // [B, M, 8]
{
    const int t = blockIdx.x * blockDim.x + threadIdx.x;
    if (t >= NSEG * OUTN) return;
    const int k = t & 7;
    const int row = t >> 3;

    const int v = vowels[row];
    float s = g_bc[k] + g_pe[v * OUTN + k];
    const float cnt = g_cnt[row];
    if (cnt > 0.0f) s += g_sum[t] / cnt;
    out[t] = s;
}

// ---------------------------------------------------------------------------
// launch
// ---------------------------------------------------------------------------
extern "C" void kernel_launch(void* const* d_in, const int* in_sizes, int n_in,
                              void* d_out, int out_size)
{
    const int*   vowels     = (const int*)d_in[0];
    const float* features   = (const float*)d_in[1];
    const int*   mora_index = (const int*)d_in[2];
    const float* emb_table  = (const float*)d_in[3];
    const float* W_mora     = (const float*)d_in[4];
    const float* b_mora     = (const float*)d_in[5];
    // d_in[6] = W_frame, d_in[7] = b_frame: dead branch, unused
    const float* W_post     = (const float*)d_in[8];
    const float* b_post     = (const float*)d_in[9];
    float* out = (float*)d_out;

    fold_kernel<<<INW + 1, 256>>>(W_mora, b_mora, W_post, b_post);
    proj_kernel<<<NPB + 2, 256>>>(features, mora_index, emb_table);
    final_kernel<<<(NSEG * OUTN + 255) / 256, 256>>>(vowels, out);
}

// round 4
// speedup vs baseline: 1.6964x; 1.2089x over previous
#include <cuda_runtime.h>
#include <cuda_bf16.h>

typedef unsigned long long ull;

// Problem shapes (fixed)
#define BN 16
#define FN 4096
#define MN 512
#define DN 256
#define VEN 64
#define HN 512
#define OUTN 8
#define VN 50
#define INW (VEN + DN)   // 320
#define NSEG (BN * MN)   // 8192

#define NPB 512          // proj main blocks (4096 warps x 16 frames = 65536 frames)
#define FRPW 16          // frames per warp (contiguous)

// ---------------------------------------------------------------------------
// Device scratch (allocation-free)
// ---------------------------------------------------------------------------
__device__ __align__(16) ull   g_Wf[128 * OUTN];       // feature weights, f32x2 pairs:
                                                       // g_Wf[jp*8+k] = (Wc[64+2jp][k], Wc[64+2jp+1][k])
__device__ __align__(16) float g_WcEmb[VEN * OUTN];    // emb rows of Wc: [j][k]
__device__ __align__(16) float g_pe[VN * OUTN];        // per-vowel emb projection
__device__ __align__(16) float g_bc[OUTN];             // combined bias
__device__ __align__(16) float g_sum[NSEG * OUTN];     // segment sums of projected frames
__device__ __align__(16) float g_cnt[NSEG];            // segment counts

// ---------------------------------------------------------------------------
// f32x2 packed FMA (Blackwell)
// ---------------------------------------------------------------------------
__device__ __forceinline__ ull fma2(ull a, ull b, ull c) {
    ull d;
    asm("fma.rn.f32x2 %0, %1, %2, %3;" : "=l"(d) : "l"(a), "l"(b), "l"(c));
    return d;
}

// ---------------------------------------------------------------------------
// Transposed warp reduction: input v[0..7] per lane (k-indexed partials),
// output: every lane returns full warp-sum for k = lane & 7. 9 shuffles.
// ---------------------------------------------------------------------------
__device__ __forceinline__ float warp_reduce_k(const float v[8], int lane) {
    const unsigned FULL = 0xFFFFFFFFu;
    float nv[4];
    const int b0 = lane & 1;
#pragma unroll
    for (int i = 0; i < 4; i++) {
        float keep = b0 ? v[2 * i + 1] : v[2 * i];
        float send = b0 ? v[2 * i]     : v[2 * i + 1];
        nv[i] = keep + __shfl_xor_sync(FULL, send, 1);
    }
    const int b1 = (lane >> 1) & 1;
    float mv[2];
#pragma unroll
    for (int i = 0; i < 2; i++) {
        float keep = b1 ? nv[2 * i + 1] : nv[2 * i];
        float send = b1 ? nv[2 * i]     : nv[2 * i + 1];
        mv[i] = keep + __shfl_xor_sync(FULL, send, 2);
    }
    const int b2 = (lane >> 2) & 1;
    float keep = b2 ? mv[1] : mv[0];
    float send = b2 ? mv[0] : mv[1];
    float s = keep + __shfl_xor_sync(FULL, send, 4);
    s += __shfl_xor_sync(FULL, s, 8);
    s += __shfl_xor_sync(FULL, s, 16);
    return s;   // k = lane & 7
}

// ---------------------------------------------------------------------------
// Kernel A: fold Wc = W_mora @ W_post + bc. 41 blocks x 8 warps, warp-per-row.
// W_post staged in smem once per block; lane l covers h = l + 32j (coalesced).
// ---------------------------------------------------------------------------
__global__ __launch_bounds__(256) void fold_kernel(
    const float* __restrict__ W_mora,   // [320, 512]
    const float* __restrict__ b_mora,   // [512]
    const float* __restrict__ W_post,   // [512, 8]
    const float* __restrict__ b_post)   // [8]
{
    __shared__ float sWp[HN * OUTN];    // 16 KB
    const int tid = threadIdx.x;
    const int lane = tid & 31;
    const int wrp = tid >> 5;           // 0..7

    for (int j = tid; j < HN * OUTN / 4; j += 256)
        ((float4*)sWp)[j] = ((const float4*)W_post)[j];
    __syncthreads();

    const int i = blockIdx.x * 8 + wrp; // row id; i == INW -> bias row
    if (i > INW) return;

    const float* src = (i < INW) ? (W_mora + (size_t)i * HN) : b_mora;

    float acc[8];
#pragma unroll
    for (int k = 0; k < 8; k++) acc[k] = 0.0f;

#pragma unroll
    for (int j = 0; j < 16; j++) {
        const int h = lane + 32 * j;
        const float a = src[h];
        const float4* wp = (const float4*)(sWp + h * OUTN);
        float4 p0 = wp[0], p1 = wp[1];
        acc[0] += a * p0.x; acc[1] += a * p0.y; acc[2] += a * p0.z; acc[3] += a * p0.w;
        acc[4] += a * p1.x; acc[5] += a * p1.y; acc[6] += a * p1.z; acc[7] += a * p1.w;
    }

    float s = warp_reduce_k(acc, lane);
    if (lane < 8) {
        if (i < VEN) {
            g_WcEmb[i * OUTN + lane] = s;
        } else if (i < INW) {
            const int j = i - VEN;
            ((float*)g_Wf)[((j >> 1) * OUTN + lane) * 2 + (j & 1)] = s;
        } else {
            g_bc[lane] = s + b_post[lane];
        }
    }
}

__device__ __forceinline__ void flush_seg(const ull racc[8], float fcnt,
                                          int seg, int lane) {
    float v[8];
#pragma unroll
    for (int k = 0; k < 8; k++) {
        float lo = __int_as_float((int)(racc[k] & 0xFFFFFFFFull));
        float hi = __int_as_float((int)(racc[k] >> 32));
        v[k] = lo + hi;
    }
    float s = warp_reduce_k(v, lane);
    if (lane < 8) atomicAdd(g_sum + seg * OUTN + lane, s);
    else if (lane == 8) atomicAdd(g_cnt + seg, fcnt);
}

// ---------------------------------------------------------------------------
// Kernel B: project frames to 8 dims (f32x2 FMA), 4-frame load batching,
// preloaded mora indices, run-length segment batching, atomic scatter.
// Extra blocks compute per-vowel embedding projection.
// ---------------------------------------------------------------------------
__global__ __launch_bounds__(256) void proj_kernel(
    const float* __restrict__ features,   // [B, F, D]
    const int* __restrict__ mora_index,   // [B, F]
    const float* __restrict__ emb_table)  // [V, VE]
{
    const unsigned FULL = 0xFFFFFFFFu;

    if (blockIdx.x >= NPB) {
        // per-vowel embedding projection: pe[v][k] = emb[v] . WcEmb[:,k]
        const int gt = (blockIdx.x - NPB) * 256 + threadIdx.x;
        if (gt < VN * OUTN) {
            const int v = gt >> 3, k = gt & 7;
            const float* e = emb_table + v * VEN;
            float s = 0.0f;
#pragma unroll 8
            for (int j = 0; j < VEN; j++) s += e[j] * g_WcEmb[j * OUTN + k];
            g_pe[gt] = s;
        }
        return;
    }

    const int lane = threadIdx.x & 31;
    const int warp = (blockIdx.x * 256 + threadIdx.x) >> 5;   // 0..4095

    // preload this lane's weight slice: rows jp in {2l, 2l+1, 64+2l, 64+2l+1}
    ull w[4][8];
    {
        const int jps0 = 2 * lane, jps2 = 64 + 2 * lane;
        const ulonglong2* Wf2 = (const ulonglong2*)g_Wf;
#pragma unroll
        for (int r = 0; r < 4; r++) {
            const int jp = (r < 2) ? (jps0 + r) : (jps2 + r - 2);
            const ulonglong2* row = Wf2 + jp * 4;   // 8 f32x2 = 4x 16B
#pragma unroll
            for (int q = 0; q < 4; q++) {
                ulonglong2 t = row[q];
                w[r][2 * q] = t.x; w[r][2 * q + 1] = t.y;
            }
        }
    }

    const int base = warp * FRPW;      // 16 contiguous frames; never crosses b
    const int b = base >> 12;          // / FN

    // preload the 16 mora indices for this warp (coalesced, one LDG)
    const int myidx = mora_index[base + (lane & 15)];

    ull racc[8];
#pragma unroll
    for (int k = 0; k < 8; k++) racc[k] = 0ull;
    float fcnt = 0.0f;
    int curm = __shfl_sync(FULL, myidx, 0);

    const ulonglong2* fr = (const ulonglong2*)(features + (size_t)base * DN);

#pragma unroll
    for (int it0 = 0; it0 < FRPW; it0 += 4) {
        // batch loads: 8 back-to-back LDG.128 (MLP_p1 = 8)
        ulonglong2 xa[4], xb[4];
#pragma unroll
        for (int j = 0; j < 4; j++) {
            xa[j] = fr[(it0 + j) * 64 + lane];
            xb[j] = fr[(it0 + j) * 64 + 32 + lane];
        }
#pragma unroll
        for (int j = 0; j < 4; j++) {
            const int m = __shfl_sync(FULL, myidx, it0 + j);
            if (m != curm) {                   // warp-uniform
                flush_seg(racc, fcnt, (b << 9) + curm, lane);
#pragma unroll
                for (int k = 0; k < 8; k++) racc[k] = 0ull;
                fcnt = 0.0f;
                curm = m;
            }
#pragma unroll
            for (int k = 0; k < 8; k++) {
                racc[k] = fma2(xa[j].x, w[0][k],
                          fma2(xa[j].y, w[1][k],
                          fma2(xb[j].x, w[2][k],
                          fma2(xb[j].y, w[3][k], racc[k]))));
            }
            fcnt += 1.0f;
        }
    }
    flush_seg(racc, fcnt, (b << 9) + curm, lane);
}

// ---------------------------------------------------------------------------
// Kernel C: finalize, thread-per-row, vectorized:
// out[row][k] = bc[k] + pe[vowel][k] + sum[row][k] * (cnt>0 ? 1/cnt : 0)
// ---------------------------------------------------------------------------
__global__ __launch_bounds__(256) void final_kernel(
    const int* __restrict__ vowels,       // [B, M]
    float* __restrict__ out)              // [B, M, 8]
{
    const int row = blockIdx.x * blockDim.x + threadIdx.x;
    if (row >= NSEG) return;

    const int v = vowels[row];
    const float4 b0 = ((const float4*)g_bc)[0];
    const float4 b1 = ((const float4*)g_bc)[1];
    const float4 p0 = ((const float4*)g_pe)[v * 2];
    const float4 p1 = ((const float4*)g_pe)[v * 2 + 1];
    const float4 s0 = ((const float4*)g_sum)[row * 2];
    const float4 s1 = ((const float4*)g_sum)[row * 2 + 1];
    const float cnt = g_cnt[row];
    const float inv = (cnt > 0.0f) ? (1.0f / cnt) : 0.0f;

    float4 o0, o1;
    o0.x = b0.x + p0.x + s0.x * inv; o0.y = b0.y + p0.y + s0.y * inv;
    o0.z = b0.z + p0.z + s0.z * inv; o0.w = b0.w + p0.w + s0.w * inv;
    o1.x = b1.x + p1.x + s1.x * inv; o1.y = b1.y + p1.y + s1.y * inv;
    o1.z = b1.z + p1.z + s1.z * inv; o1.w = b1.w + p1.w + s1.w * inv;

    ((float4*)out)[row * 2]     = o0;
    ((float4*)out)[row * 2 + 1] = o1;
}

// ---------------------------------------------------------------------------
// launch
// ---------------------------------------------------------------------------
extern "C" void kernel_launch(void* const* d_in, const int* in_sizes, int n_in,
                              void* d_out, int out_size)
{
    const int*   vowels     = (const int*)d_in[0];
    const float* features   = (const float*)d_in[1];
    const int*   mora_index = (const int*)d_in[2];
    const float* emb_table  = (const float*)d_in[3];
    const float* W_mora     = (const float*)d_in[4];
    const float* b_mora     = (const float*)d_in[5];
    // d_in[6] = W_frame, d_in[7] = b_frame: dead branch, unused
    const float* W_post     = (const float*)d_in[8];
    const float* b_post     = (const float*)d_in[9];
    float* out = (float*)d_out;

    // zero accumulators via memset nodes (graph-capturable, no allocations)
    void* p_sum = nullptr;
    void* p_cnt = nullptr;
    cudaGetSymbolAddress(&p_sum, g_sum);
    cudaGetSymbolAddress(&p_cnt, g_cnt);
    cudaMemsetAsync(p_sum, 0, NSEG * OUTN * sizeof(float));
    cudaMemsetAsync(p_cnt, 0, NSEG * sizeof(float));

    fold_kernel<<<41, 256>>>(W_mora, b_mora, W_post, b_post);
    proj_kernel<<<NPB + 2, 256>>>(features, mora_index, emb_table);
    final_kernel<<<(NSEG + 255) / 256, 256>>>(vowels, out);
}

// round 5
// speedup vs baseline: 1.7113x; 1.0088x over previous
#include <cuda_runtime.h>
#include <cuda_bf16.h>

typedef unsigned long long ull;

// Problem shapes (fixed)
#define BN 16
#define FN 4096
#define MN 512
#define DN 256
#define VEN 64
#define HN 512
#define OUTN 8
#define VN 50
#define INW (VEN + DN)   // 320
#define NSEG (BN * MN)   // 8192

#define NPB 512          // proj main blocks (4096 warps x 16 frames = 65536 frames)
#define FRPW 16          // frames per warp (contiguous)

// ---------------------------------------------------------------------------
// One contiguous scratch array (single memset node zeroes [0, OFF_PE)).
//   sum   [NSEG*OUTN]           @ 0
//   cnt   [NSEG]                @ 65536
//   Wf    [128*8 ull = 2048 f]  @ 73728   k-major: ull[k*128+jp] = (Wc[64+2jp][k], Wc[64+2jp+1][k])
//   WcEmb [VEN*OUTN = 512 f]    @ 75776
//   bc    [8]                   @ 76288
//   pe    [VN*OUTN = 400 f]     @ 76296   (no zero needed)
// ---------------------------------------------------------------------------
#define OFF_SUM   0
#define OFF_CNT   65536
#define OFF_WF    73728
#define OFF_WCEMB 75776
#define OFF_BC    76288
#define OFF_PE    76296
#define SCR_TOTAL 76696

__device__ __align__(16) float g_scr[SCR_TOTAL];

__device__ __forceinline__ ull fma2(ull a, ull b, ull c) {
    ull d;
    asm("fma.rn.f32x2 %0, %1, %2, %3;" : "=l"(d) : "l"(a), "l"(b), "l"(c));
    return d;
}
__device__ __forceinline__ ull add2(ull a, ull b) {
    ull d;
    asm("add.rn.f32x2 %0, %1, %2;" : "=l"(d) : "l"(a), "l"(b));
    return d;
}

// ---------------------------------------------------------------------------
// Transposed warp reduction: input v[0..7] per lane (k-indexed partials),
// output: every lane returns full warp-sum for k = lane & 7. 9 shuffles.
// ---------------------------------------------------------------------------
__device__ __forceinline__ float warp_reduce_k(const float v[8], int lane) {
    const unsigned FULL = 0xFFFFFFFFu;
    float nv[4];
    const int b0 = lane & 1;
#pragma unroll
    for (int i = 0; i < 4; i++) {
        float keep = b0 ? v[2 * i + 1] : v[2 * i];
        float send = b0 ? v[2 * i]     : v[2 * i + 1];
        nv[i] = keep + __shfl_xor_sync(FULL, send, 1);
    }
    const int b1 = (lane >> 1) & 1;
    float mv[2];
#pragma unroll
    for (int i = 0; i < 2; i++) {
        float keep = b1 ? nv[2 * i + 1] : nv[2 * i];
        float send = b1 ? nv[2 * i]     : nv[2 * i + 1];
        mv[i] = keep + __shfl_xor_sync(FULL, send, 2);
    }
    const int b2 = (lane >> 2) & 1;
    float keep = b2 ? mv[1] : mv[0];
    float send = b2 ? mv[0] : mv[1];
    float s = keep + __shfl_xor_sync(FULL, send, 4);
    s += __shfl_xor_sync(FULL, s, 8);
    s += __shfl_xor_sync(FULL, s, 16);
    return s;   // k = lane & 7
}

// ---------------------------------------------------------------------------
// Kernel A: fold Wc = W_mora @ W_post + bc. Warp-per-(row, H-half): 642 warps.
// No smem, no barrier; W_post read direct (L2-hot); atomicAdd into zeroed scr.
// ---------------------------------------------------------------------------
__global__ __launch_bounds__(256) void fold_kernel(
    const float* __restrict__ W_mora,   // [320, 512]
    const float* __restrict__ b_mora,   // [512]
    const float* __restrict__ W_post,   // [512, 8]
    const float* __restrict__ b_post)   // [8]
{
    const int tid = threadIdx.x;
    const int lane = tid & 31;
    const int w = blockIdx.x * 8 + (tid >> 5);   // 0..647
    const int i = w >> 1;                        // row 0..323
    const int half = w & 1;
    if (i > INW) return;

    const float* src = (i < INW) ? (W_mora + (size_t)i * HN) : b_mora;

    float acc[8];
#pragma unroll
    for (int k = 0; k < 8; k++) acc[k] = 0.0f;

#pragma unroll
    for (int j = 0; j < 8; j++) {
        const int h = half * 256 + 32 * j + lane;
        const float a = src[h];
        const float4* wp = (const float4*)(W_post + h * OUTN);
        float4 p0 = wp[0], p1 = wp[1];
        acc[0] += a * p0.x; acc[1] += a * p0.y; acc[2] += a * p0.z; acc[3] += a * p0.w;
        acc[4] += a * p1.x; acc[5] += a * p1.y; acc[6] += a * p1.z; acc[7] += a * p1.w;
    }

    float s = warp_reduce_k(acc, lane);
    if (lane < 8) {
        const int k = lane;
        if (i < VEN) {
            atomicAdd(g_scr + OFF_WCEMB + i * OUTN + k, s);
        } else if (i < INW) {
            const int j = i - VEN;
            // float view of k-major ull layout: ull idx = k*128 + (j>>1), sub = j&1
            atomicAdd(g_scr + OFF_WF + (k * 128 + (j >> 1)) * 2 + (j & 1), s);
        } else {
            atomicAdd(g_scr + OFF_BC + k, s + (half == 0 ? b_post[k] : 0.0f));
        }
    }
}

// ---------------------------------------------------------------------------
// Flush: project 8-per-lane run-sum (racc, 4 f32x2) to 8 outputs using smem
// weights (k-major, conflict-free LDS.128), transposed reduce, atomic scatter.
// __noinline__ keeps the hot loop lean (rare path).
// ---------------------------------------------------------------------------
__device__ __noinline__ void flush_seg(const ull* __restrict__ sWf,
                                       const ull* __restrict__ racc,
                                       float fcnt, int seg, int lane) {
    const int p0 = 2 * lane, p1 = 64 + 2 * lane;
    const ull zero = 0ull;
    float v[8];
#pragma unroll
    for (int k = 0; k < 8; k++) {
        ulonglong2 wa = *(const ulonglong2*)(sWf + k * 128 + p0);
        ulonglong2 wb = *(const ulonglong2*)(sWf + k * 128 + p1);
        ull t = fma2(racc[0], wa.x,
                fma2(racc[1], wa.y,
                fma2(racc[2], wb.x,
                fma2(racc[3], wb.y, zero))));
        float lo = __int_as_float((int)(t & 0xFFFFFFFFull));
        float hi = __int_as_float((int)(t >> 32));
        v[k] = lo + hi;
    }
    float s = warp_reduce_k(v, lane);
    if (lane < 8) atomicAdd(g_scr + OFF_SUM + seg * OUTN + lane, s);
    else if (lane == 8) atomicAdd(g_scr + OFF_CNT + seg, fcnt);
}

// ---------------------------------------------------------------------------
// Kernel B: per-frame 8-dim-per-lane running sums (4x add.f32x2/frame),
// 4-frame batched LDG.128, preloaded mora indices, flush per run.
// Extra blocks compute per-vowel embedding projection.
// ---------------------------------------------------------------------------
__global__ __launch_bounds__(256) void proj_kernel(
    const float* __restrict__ features,   // [B, F, D]
    const int* __restrict__ mora_index,   // [B, F]
    const float* __restrict__ emb_table)  // [V, VE]
{
    const unsigned FULL = 0xFFFFFFFFu;

    if (blockIdx.x >= NPB) {
        // per-vowel embedding projection: pe[v][k] = emb[v] . WcEmb[:,k]
        const int gt = (blockIdx.x - NPB) * 256 + threadIdx.x;
        if (gt < VN * OUTN) {
            const int v = gt >> 3, k = gt & 7;
            const float* e = emb_table + v * VEN;
            const float* we = g_scr + OFF_WCEMB;
            float s = 0.0f;
#pragma unroll 8
            for (int j = 0; j < VEN; j++) s += e[j] * we[j * OUTN + k];
            g_scr[OFF_PE + gt] = s;
        }
        return;
    }

    __shared__ __align__(16) ull sWf[128 * 8];   // 8 KB, k-major
    const int tid = threadIdx.x;
    for (int j = tid; j < 128 * 8 / 2; j += 256)
        ((ulonglong2*)sWf)[j] = ((const ulonglong2*)(g_scr + OFF_WF))[j];
    __syncthreads();

    const int lane = tid & 31;
    const int warp = (blockIdx.x * 256 + tid) >> 5;   // 0..4095
    const int base = warp * FRPW;                     // 16 contiguous frames
    const int b = base >> 12;                         // / FN

    // preload the 16 mora indices for this warp (one coalesced LDG)
    const int myidx = mora_index[base + (lane & 15)];

    ull racc[4];
#pragma unroll
    for (int q = 0; q < 4; q++) racc[q] = 0ull;
    float fcnt = 0.0f;
    int curm = __shfl_sync(FULL, myidx, 0);

    const ulonglong2* fr = (const ulonglong2*)(features + (size_t)base * DN);

#pragma unroll
    for (int it0 = 0; it0 < FRPW; it0 += 4) {
        // batch loads: 8 back-to-back LDG.128 (MLP_p1 = 8)
        ulonglong2 xa[4], xb[4];
#pragma unroll
        for (int j = 0; j < 4; j++) {
            xa[j] = fr[(it0 + j) * 64 + lane];        // dims 4l..4l+3
            xb[j] = fr[(it0 + j) * 64 + 32 + lane];   // dims 128+4l..128+4l+3
        }
#pragma unroll
        for (int j = 0; j < 4; j++) {
            const int m = __shfl_sync(FULL, myidx, it0 + j);
            if (m != curm) {                          // warp-uniform
                flush_seg(sWf, racc, fcnt, (b << 9) + curm, lane);
#pragma unroll
                for (int q = 0; q < 4; q++) racc[q] = 0ull;
                fcnt = 0.0f;
                curm = m;
            }
            racc[0] = add2(racc[0], xa[j].x);
            racc[1] = add2(racc[1], xa[j].y);
            racc[2] = add2(racc[2], xb[j].x);
            racc[3] = add2(racc[3], xb[j].y);
            fcnt += 1.0f;
        }
    }
    flush_seg(sWf, racc, fcnt, (b << 9) + curm, lane);
}

// ---------------------------------------------------------------------------
// Kernel C: finalize, thread-per-row, vectorized:
// out[row][k] = bc[k] + pe[vowel][k] + sum[row][k] * (cnt>0 ? 1/cnt : 0)
// ---------------------------------------------------------------------------
__global__ __launch_bounds__(256) void final_kernel(
    const int* __restrict__ vowels,       // [B, M]
    float* __restrict__ out)              // [B, M, 8]
{
    const int row = blockIdx.x * blockDim.x + threadIdx.x;
    if (row >= NSEG) return;

    const int v = vowels[row];
    const float4 b0 = ((const float4*)(g_scr + OFF_BC))[0];
    const float4 b1 = ((const float4*)(g_scr + OFF_BC))[1];
    const float4 p0 = ((const float4*)(g_scr + OFF_PE))[v * 2];
    const float4 p1 = ((const float4*)(g_scr + OFF_PE))[v * 2 + 1];
    const float4 s0 = ((const float4*)(g_scr + OFF_SUM))[row * 2];
    const float4 s1 = ((const float4*)(g_scr + OFF_SUM))[row * 2 + 1];
    const float cnt = g_scr[OFF_CNT + row];
    const float inv = (cnt > 0.0f) ? (1.0f / cnt) : 0.0f;

    float4 o0, o1;
    o0.x = b0.x + p0.x + s0.x * inv; o0.y = b0.y + p0.y + s0.y * inv;
    o0.z = b0.z + p0.z + s0.z * inv; o0.w = b0.w + p0.w + s0.w * inv;
    o1.x = b1.x + p1.x + s1.x * inv; o1.y = b1.y + p1.y + s1.y * inv;
    o1.z = b1.z + p1.z + s1.z * inv; o1.w = b1.w + p1.w + s1.w * inv;

    ((float4*)out)[row * 2]     = o0;
    ((float4*)out)[row * 2 + 1] = o1;
}

// ---------------------------------------------------------------------------
// launch
// ---------------------------------------------------------------------------
extern "C" void kernel_launch(void* const* d_in, const int* in_sizes, int n_in,
                              void* d_out, int out_size)
{
    const int*   vowels     = (const int*)d_in[0];
    const float* features   = (const float*)d_in[1];
    const int*   mora_index = (const int*)d_in[2];
    const float* emb_table  = (const float*)d_in[3];
    const float* W_mora     = (const float*)d_in[4];
    const float* b_mora     = (const float*)d_in[5];
    // d_in[6] = W_frame, d_in[7] = b_frame: dead branch, unused
    const float* W_post     = (const float*)d_in[8];
    const float* b_post     = (const float*)d_in[9];
    float* out = (float*)d_out;

    // single memset node zeroes sum/cnt/Wf/WcEmb/bc (fold uses atomicAdd)
    void* p_scr = nullptr;
    cudaGetSymbolAddress(&p_scr, g_scr);
    cudaMemsetAsync(p_scr, 0, OFF_PE * sizeof(float));

    fold_kernel<<<81, 256>>>(W_mora, b_mora, W_post, b_post);
    proj_kernel<<<NPB + 2, 256>>>(features, mora_index, emb_table);
    final_kernel<<<(NSEG + 255) / 256, 256>>>(vowels, out);
}